// round 9
// baseline (speedup 1.0000x reference)
#include <cuda_runtime.h>
#include <cuda_bf16.h>
#include <cstdint>

#define D 128
#define NMAX 50000
#define TTYPES 4
#define AST 136                      // bf16 elems per smem row (ldmatrix pad)

// k_final smem layout (64-row tiles)
#define F_A 17408                    // 64*136*2
#define F_B 34816                    // 128*136*2
#define F_SMEM (2 * F_A + 2 * F_B)   // 104448

// k_edge_mlp persistent layout (128-row tiles)
#define M_A 34816                    // 128*136*2 (one split half)
#define M_SMEM (4 * M_A)             // Ah, Al, Bh, Bl = 139264

// Scratch (device globals: allocation-free rule)
__device__ float g_A[(size_t)TTYPES * NMAX * D];
__device__ float g_S[(size_t)NMAX * D];
__device__ int   g_cnt[TTYPES * NMAX];
// pre-split weights: [0..3]=W_types, [4]=W_e2, [5]=W_self, [6]=W1
__device__ __nv_bfloat16 g_Wh[7 * D * D];
__device__ __nv_bfloat16 g_Wl[7 * D * D];

// ---------------------------------------------------------------------------
__device__ __forceinline__ uint32_t smem_u32(const void* p) {
    return (uint32_t)__cvta_generic_to_shared(p);
}
__device__ __forceinline__ void split_bf(float a, __nv_bfloat16& h, __nv_bfloat16& l) {
    h = __float2bfloat16_rn(a);
    l = __float2bfloat16_rn(a - __bfloat162float(h));
}
__device__ __forceinline__ void store4_split(__nv_bfloat16* Hrow, __nv_bfloat16* Lrow,
                                             int c, float4 v) {
    __nv_bfloat16 h0, l0, h1, l1, h2, l2, h3, l3;
    split_bf(v.x, h0, l0); split_bf(v.y, h1, l1);
    split_bf(v.z, h2, l2); split_bf(v.w, h3, l3);
    *(__nv_bfloat162*)(Hrow + c)     = __halves2bfloat162(h0, h1);
    *(__nv_bfloat162*)(Hrow + c + 2) = __halves2bfloat162(h2, h3);
    *(__nv_bfloat162*)(Lrow + c)     = __halves2bfloat162(l0, l1);
    *(__nv_bfloat162*)(Lrow + c + 2) = __halves2bfloat162(l2, l3);
}

#define LDMX4(r0, r1, r2, r3, addr) \
    asm volatile("ldmatrix.sync.aligned.m8n8.x4.shared.b16 {%0,%1,%2,%3},[%4];" \
                 : "=r"(r0), "=r"(r1), "=r"(r2), "=r"(r3) : "r"(addr))
#define LDMX2T(r0, r1, addr) \
    asm volatile("ldmatrix.sync.aligned.m8n8.x2.trans.shared.b16 {%0,%1},[%2];" \
                 : "=r"(r0), "=r"(r1) : "r"(addr))
#define MMA_BF16(d, a0, a1, a2, a3, b0, b1) \
    asm volatile("mma.sync.aligned.m16n8k16.row.col.f32.bf16.bf16.f32 " \
                 "{%0,%1,%2,%3},{%4,%5,%6,%7},{%8,%9},{%0,%1,%2,%3};" \
                 : "+f"(d[0]), "+f"(d[1]), "+f"(d[2]), "+f"(d[3]) \
                 : "r"(a0), "r"(a1), "r"(a2), "r"(a3), "r"(b0), "r"(b1))
#define REDV4(ptr, v0, v1, v2, v3) \
    asm volatile("red.global.add.v4.f32 [%0], {%1,%2,%3,%4};" \
                 :: "l"(ptr), "f"(v0), "f"(v1), "f"(v2), "f"(v3) : "memory")

// Core split-2 MMA over K=128: warp covers 16 rows x 64 cols. acc[8][4].
__device__ __forceinline__ void mma_core(uint32_t aH, uint32_t bH,
                                         uint32_t aDelta, uint32_t bDelta,
                                         float acc[8][4]) {
    #pragma unroll
    for (int ks = 0; ks < 8; ks++) {
        uint32_t ao = aH + ks * 32;                  // +16 bf16 along k
        uint32_t ah0, ah1, ah2, ah3, al0, al1, al2, al3;
        LDMX4(ah0, ah1, ah2, ah3, ao);
        LDMX4(al0, al1, al2, al3, ao + aDelta);
        uint32_t br = bH + ks * (16 * AST * 2);      // +16 k-rows
        #pragma unroll
        for (int nt = 0; nt < 8; nt++) {
            uint32_t ba = br + nt * 16;
            uint32_t bh0, bh1, bl0, bl1;
            LDMX2T(bh0, bh1, ba);
            LDMX2T(bl0, bl1, ba + bDelta);
            MMA_BF16(acc[nt], al0, al1, al2, al3, bh0, bh1);
            MMA_BF16(acc[nt], ah0, ah1, ah2, ah3, bl0, bl1);
            MMA_BF16(acc[nt], ah0, ah1, ah2, ah3, bh0, bh1);
        }
    }
}

// Load pre-split weight matrix widx into smem at byte offsets bhOff/blOff.
__device__ __forceinline__ void load_B_at(char* smem, uint32_t bhOff, uint32_t blOff,
                                          int widx, int tid, int nthreads) {
    __nv_bfloat16* Bh = (__nv_bfloat16*)(smem + bhOff);
    __nv_bfloat16* Bl = (__nv_bfloat16*)(smem + blOff);
    const uint4* srcH = (const uint4*)(g_Wh + (size_t)widx * D * D);
    const uint4* srcL = (const uint4*)(g_Wl + (size_t)widx * D * D);
    for (int f = tid; f < 2048; f += nthreads) {
        int k = f >> 4, c8 = (f & 15) * 8;
        *(uint4*)(Bh + k * AST + c8) = srcH[f];
        *(uint4*)(Bl + k * AST + c8) = srcL[f];
    }
}

// ---------------------------------------------------------------------------
__global__ void k_split_w(const float* __restrict__ Wt, const float* __restrict__ We2,
                          const float* __restrict__ Wself, const float* __restrict__ W1) {
    int i = blockIdx.x * blockDim.x + threadIdx.x;
    int idx = i * 2;
    if (idx >= 7 * D * D) return;
    int m = idx / (D * D), r = idx % (D * D);
    const float* src = (m < 4) ? (Wt + (size_t)m * D * D + r)
                     : (m == 4 ? We2 + r : (m == 5 ? Wself + r : W1 + r));
    float2 v = *(const float2*)src;
    __nv_bfloat16 h0, l0, h1, l1;
    split_bf(v.x, h0, l0); split_bf(v.y, h1, l1);
    *(__nv_bfloat162*)(g_Wh + idx) = __halves2bfloat162(h0, h1);
    *(__nv_bfloat162*)(g_Wl + idx) = __halves2bfloat162(l0, l1);
}

// ---------------------------------------------------------------------------
__global__ void k_zero(int N) {
    size_t nA4 = (size_t)TTYPES * N * D / 4;
    size_t nS4 = (size_t)N * D / 4;
    size_t nC  = (size_t)TTYPES * N;
    size_t stride = (size_t)gridDim.x * blockDim.x;
    size_t i0 = (size_t)blockIdx.x * blockDim.x + threadIdx.x;
    float4 z = make_float4(0.f, 0.f, 0.f, 0.f);
    float4* A4 = (float4*)g_A;
    float4* S4 = (float4*)g_S;
    for (size_t i = i0; i < nA4; i += stride) A4[i] = z;
    for (size_t i = i0; i < nS4; i += stride) S4[i] = z;
    for (size_t i = i0; i < nC;  i += stride) g_cnt[i] = 0;
}

// ---------------------------------------------------------------------------
// One warp per edge: g_A[type][row] += x[col] (red.v4); counts.
__global__ void k_scatter(const float* __restrict__ x, const int* __restrict__ ei,
                          const int* __restrict__ et, int N, int E) {
    int w = (int)(((size_t)blockIdx.x * blockDim.x + threadIdx.x) >> 5);
    int lane = threadIdx.x & 31;
    if (w >= E) return;
    int row = __ldg(ei + w);
    int col = __ldg(ei + E + w);
    int t   = __ldg(et + w);
    float4 v = *(const float4*)(x + (size_t)col * D + lane * 4);
    float* p = g_A + ((size_t)t * N + row) * D + lane * 4;
    REDV4(p, v.x, v.y, v.z, v.w);
    if (lane == 0) atomicAdd(&g_cnt[t * N + row], 1);
}

// ---------------------------------------------------------------------------
// Persistent edge MLP: W1 resident in smem; loop over 128-edge tiles with
// register prefetch of the next tile under the MMA. 512 threads, 1 block/SM.
__device__ __forceinline__ void mlp_load_regs(float4 r[8], const float* __restrict__ ef,
                                              int tile, int ntiles, int E, int tid) {
    if (tile >= ntiles) {
        #pragma unroll
        for (int t = 0; t < 8; t++) r[t] = make_float4(0.f, 0.f, 0.f, 0.f);
        return;
    }
    size_t e0 = (size_t)tile * 128;
    #pragma unroll
    for (int t = 0; t < 8; t++) {
        int idx = tid + t * 512;
        int row = idx >> 5, c4 = (idx & 31) * 4;
        size_t e = e0 + row;
        float4 v = make_float4(0.f, 0.f, 0.f, 0.f);
        if (e < (size_t)E) v = *(const float4*)(ef + e * D + c4);
        r[t] = v;
    }
}

__global__ void __launch_bounds__(512, 1)
k_edge_mlp(const float* __restrict__ ef, const int* __restrict__ ei,
           const float* __restrict__ b1, int E, int ntiles) {
    extern __shared__ char smem[];
    __nv_bfloat16* Ah = (__nv_bfloat16*)smem;
    __nv_bfloat16* Al = (__nv_bfloat16*)(smem + M_A);
    int tid = threadIdx.x, wid = tid >> 5, lane = tid & 31;
    int rw = (wid & 7) * 16, ch = (wid >> 3) * 64;

    load_B_at(smem, 2 * M_A, 3 * M_A, 6, tid, 512);   // W1, resident
    float4 bb = __ldg((const float4*)b1 + lane);

    uint32_t aH = smem_u32(Ah + (rw + (lane & 15)) * AST + ((lane >> 4) * 8));
    uint32_t bH = smem_u32((__nv_bfloat16*)(smem + 2 * M_A) + (lane & 15) * AST + ch);

    int tile = blockIdx.x;
    float4 r[8];
    mlp_load_regs(r, ef, tile, ntiles, E, tid);

    for (; tile < ntiles; tile += gridDim.x) {
        // convert regs -> split smem A
        #pragma unroll
        for (int t = 0; t < 8; t++) {
            int idx = tid + t * 512;
            int row = idx >> 5, c4 = (idx & 31) * 4;
            store4_split(Ah + row * AST, Al + row * AST, c4, r[t]);
        }
        __syncthreads();
        // prefetch next tile (LDG latency hides under MMA)
        mlp_load_regs(r, ef, tile + (int)gridDim.x, ntiles, E, tid);

        float acc[8][4] = {};
        mma_core(aH, bH, M_A, M_A, acc);
        __syncthreads();

        // acc -> S (overlay A buffers; full rows needed for contiguous scatter)
        float* S = (float*)smem;   // [128][132]
        {
            int r0 = rw + (lane >> 2);
            int cp = (lane & 3) * 2;
            #pragma unroll
            for (int nt = 0; nt < 8; nt++) {
                int c = ch + nt * 8 + cp;
                S[r0 * 132 + c]           = acc[nt][0];
                S[r0 * 132 + c + 1]       = acc[nt][1];
                S[(r0 + 8) * 132 + c]     = acc[nt][2];
                S[(r0 + 8) * 132 + c + 1] = acc[nt][3];
            }
        }
        __syncthreads();

        // scatter: warp w handles edges [w*8, w*8+8)
        size_t e0 = (size_t)tile * 128;
        #pragma unroll
        for (int it = 0; it < 8; it++) {
            int el = wid * 8 + it;
            size_t e = e0 + el;
            if (e < (size_t)E) {
                int dst = __ldg(ei + e);
                const float* Sr = S + el * 132 + lane * 4;
                float v0 = fmaxf(Sr[0] + bb.x, 0.f);
                float v1 = fmaxf(Sr[1] + bb.y, 0.f);
                float v2 = fmaxf(Sr[2] + bb.z, 0.f);
                float v3 = fmaxf(Sr[3] + bb.w, 0.f);
                REDV4(g_S + (size_t)dst * D + lane * 4, v0, v1, v2, v3);
            }
        }
        __syncthreads();
    }
}

// ---------------------------------------------------------------------------
// out[n] = sum over 6 K-segments + count-weighted biases, LayerNorm, ReLU.
// 64-node tiles, 2 blocks/SM.
__global__ void __launch_bounds__(256, 2)
k_final(const float* __restrict__ x,
        const float* __restrict__ b_types, const float* __restrict__ b_self,
        const float* __restrict__ b_e2,
        const float* __restrict__ ln_g, const float* __restrict__ ln_b,
        float* __restrict__ out, int N) {
    extern __shared__ char smem[];
    __shared__ float Ps[1024];
    __nv_bfloat16* Ah = (__nv_bfloat16*)smem;
    __nv_bfloat16* Al = (__nv_bfloat16*)(smem + F_A);
    int tid = threadIdx.x, wid = tid >> 5, lane = tid & 31;
    int n0 = blockIdx.x * 64;
    int rw = (wid & 3) * 16, ch = (wid >> 2) * 64;

    for (int f = tid; f < 1024; f += 256) {
        float v;
        if (f < 512)      v = b_types[f];
        else if (f < 640) v = b_e2[f - 512];
        else if (f < 768) v = b_self[f - 640];
        else if (f < 896) v = ln_g[f - 768];
        else              v = ln_b[f - 896];
        Ps[f] = v;
    }

    uint32_t aH = smem_u32(Ah + (rw + (lane & 15)) * AST + ((lane >> 4) * 8));
    uint32_t bH = smem_u32((__nv_bfloat16*)(smem + 2 * F_A) + (lane & 15) * AST + ch);

    float acc[8][4] = {};
    for (int seg = 0; seg < 6; seg++) {
        const float* Ab = (seg < 4) ? (g_A + (size_t)seg * N * D)
                                    : (seg == 4 ? g_S : x);
        __syncthreads();
        for (int idx = tid; idx < 64 * 32; idx += 256) {
            int r = idx >> 5, c4 = (idx & 31) * 4;
            float4 v = make_float4(0.f, 0.f, 0.f, 0.f);
            int n = n0 + r;
            if (n < N) v = *(const float4*)(Ab + (size_t)n * D + c4);
            store4_split(Ah + r * AST, Al + r * AST, c4, v);
        }
        load_B_at(smem, 2 * F_A, 2 * F_A + F_B, seg, tid, 256);
        __syncthreads();
        mma_core(aH, bH, F_A, F_B, acc);
    }

    // Epilogue via smem round-trip (full rows needed for LayerNorm).
    __syncthreads();
    float* S = (float*)smem;   // [64][132]
    {
        int r0 = rw + (lane >> 2);
        int cp = (lane & 3) * 2;
        #pragma unroll
        for (int nt = 0; nt < 8; nt++) {
            int c = ch + nt * 8 + cp;
            S[r0 * 132 + c]           = acc[nt][0];
            S[r0 * 132 + c + 1]       = acc[nt][1];
            S[(r0 + 8) * 132 + c]     = acc[nt][2];
            S[(r0 + 8) * 132 + c + 1] = acc[nt][3];
        }
    }
    __syncthreads();

    for (int it = 0; it < 8; it++) {
        int r = wid * 8 + it;
        int n = n0 + r;
        bool valid = n < N;
        float c0 = 0.f, c1 = 0.f, c2 = 0.f, c3 = 0.f;
        if (valid) {
            c0 = (float)__ldg(&g_cnt[0 * N + n]);
            c1 = (float)__ldg(&g_cnt[1 * N + n]);
            c2 = (float)__ldg(&g_cnt[2 * N + n]);
            c3 = (float)__ldg(&g_cnt[3 * N + n]);
        }
        float ct = c0 + c1 + c2 + c3;
        float v[4];
        float s1 = 0.f, s2 = 0.f;
        #pragma unroll
        for (int j = 0; j < 4; j++) {
            int col = lane * 4 + j;
            float val = S[r * 132 + col]
                + c0 * Ps[0 * D + col] + c1 * Ps[1 * D + col]
                + c2 * Ps[2 * D + col] + c3 * Ps[3 * D + col]
                + ct * Ps[512 + col] + Ps[640 + col];
            v[j] = val;
            s1 += val;
            s2 += val * val;
        }
        #pragma unroll
        for (int m = 1; m < 32; m <<= 1) {
            s1 += __shfl_xor_sync(0xffffffff, s1, m);
            s2 += __shfl_xor_sync(0xffffffff, s2, m);
        }
        float mean = s1 * (1.f / D);
        float var  = s2 * (1.f / D) - mean * mean;
        float inv  = rsqrtf(var + 1e-5f);
        if (valid) {
            float4 o;
            #pragma unroll
            for (int j = 0; j < 4; j++) {
                int col = lane * 4 + j;
                float rres = (v[j] - mean) * inv * Ps[768 + col] + Ps[896 + col];
                (&o.x)[j] = rres > 0.f ? rres : 0.f;
            }
            *(float4*)(out + (size_t)n * D + lane * 4) = o;
        }
    }
}

// ---------------------------------------------------------------------------
extern "C" void kernel_launch(void* const* d_in, const int* in_sizes, int n_in,
                              void* d_out, int out_size) {
    const float* x   = (const float*)d_in[0];
    const int*   ei  = (const int*)d_in[1];
    const int*   et  = (const int*)d_in[2];
    const float* ef  = (const float*)d_in[3];
    const float* Wt  = (const float*)d_in[4];
    const float* bt  = (const float*)d_in[5];
    const float* Ws  = (const float*)d_in[6];
    const float* bs  = (const float*)d_in[7];
    const float* W1  = (const float*)d_in[8];
    const float* b1  = (const float*)d_in[9];
    const float* W2  = (const float*)d_in[10];
    const float* b2  = (const float*)d_in[11];
    const float* lg  = (const float*)d_in[12];
    const float* lb  = (const float*)d_in[13];
    float* out = (float*)d_out;

    int N = in_sizes[0] / D;
    int E = in_sizes[2];
    int ntiles = (E + 127) / 128;
    int mlp_grid = ntiles < 148 ? ntiles : 148;

    cudaFuncSetAttribute(k_edge_mlp, cudaFuncAttributeMaxDynamicSharedMemorySize, M_SMEM);
    cudaFuncSetAttribute(k_final,    cudaFuncAttributeMaxDynamicSharedMemorySize, F_SMEM);

    k_split_w<<<(7 * D * D / 2 + 255) / 256, 256>>>(Wt, W2, Ws, W1);
    k_zero<<<2048, 256>>>(N);
    k_scatter<<<(E + 7) / 8, 256>>>(x, ei, et, N, E);
    k_edge_mlp<<<mlp_grid, 512, M_SMEM>>>(ef, ei, b1, E, ntiles);
    k_final<<<(N + 63) / 64, 256, F_SMEM>>>(x, bt, bs, b2, lg, lb, out, N);
}

// round 11
// speedup vs baseline: 1.2721x; 1.2721x over previous
#include <cuda_runtime.h>
#include <cuda_bf16.h>
#include <cstdint>

#define D 128
#define NMAX 50000
#define TTYPES 4
#define AST 136                      // bf16 elems per smem row (ldmatrix pad)

// k_final smem layout (64-row tiles, 2 blocks/SM)
#define F_A 17408                    // 64*136*2
#define F_B 34816                    // 128*136*2
#define F_SMEM (2 * F_A + 2 * F_B)   // 104448

// k_edge_mlp persistent layout (128-row tiles, reg-resident B)
// startup: W1 staged at [0, 69632) ; steady: Ah [0,34816) Al [34816,69632)
//          S f32 [69632, 137216)
#define P_HALF 34816
#define P_S    69632
#define P_SMEM 137216

// Scratch (device globals: allocation-free rule)
__device__ float g_A[(size_t)TTYPES * NMAX * D];   // per-type scatter of x[col]
__device__ float g_S[(size_t)NMAX * D];            // scatter of relu(ef@W1+b1)
__device__ int   g_cnt[TTYPES * NMAX];             // per (type,node) edge counts
// pre-split weights: [0..3]=W_types, [4]=W_e2, [5]=W_self, [6]=W1
__device__ __nv_bfloat16 g_Wh[7 * D * D];
__device__ __nv_bfloat16 g_Wl[7 * D * D];

// ---------------------------------------------------------------------------
__device__ __forceinline__ uint32_t smem_u32(const void* p) {
    return (uint32_t)__cvta_generic_to_shared(p);
}
__device__ __forceinline__ void split_bf(float a, __nv_bfloat16& h, __nv_bfloat16& l) {
    h = __float2bfloat16_rn(a);
    l = __float2bfloat16_rn(a - __bfloat162float(h));
}
__device__ __forceinline__ void store4_split(__nv_bfloat16* Hrow, __nv_bfloat16* Lrow,
                                             int c, float4 v) {
    __nv_bfloat16 h0, l0, h1, l1, h2, l2, h3, l3;
    split_bf(v.x, h0, l0); split_bf(v.y, h1, l1);
    split_bf(v.z, h2, l2); split_bf(v.w, h3, l3);
    *(__nv_bfloat162*)(Hrow + c)     = __halves2bfloat162(h0, h1);
    *(__nv_bfloat162*)(Hrow + c + 2) = __halves2bfloat162(h2, h3);
    *(__nv_bfloat162*)(Lrow + c)     = __halves2bfloat162(l0, l1);
    *(__nv_bfloat162*)(Lrow + c + 2) = __halves2bfloat162(l2, l3);
}

#define LDMX4(r0, r1, r2, r3, addr) \
    asm volatile("ldmatrix.sync.aligned.m8n8.x4.shared.b16 {%0,%1,%2,%3},[%4];" \
                 : "=r"(r0), "=r"(r1), "=r"(r2), "=r"(r3) : "r"(addr))
#define LDMX2T(r0, r1, addr) \
    asm volatile("ldmatrix.sync.aligned.m8n8.x2.trans.shared.b16 {%0,%1},[%2];" \
                 : "=r"(r0), "=r"(r1) : "r"(addr))
#define MMA_BF16(d, a0, a1, a2, a3, b0, b1) \
    asm volatile("mma.sync.aligned.m16n8k16.row.col.f32.bf16.bf16.f32 " \
                 "{%0,%1,%2,%3},{%4,%5,%6,%7},{%8,%9},{%0,%1,%2,%3};" \
                 : "+f"(d[0]), "+f"(d[1]), "+f"(d[2]), "+f"(d[3]) \
                 : "r"(a0), "r"(a1), "r"(a2), "r"(a3), "r"(b0), "r"(b1))
#define REDV4(ptr, v0, v1, v2, v3) \
    asm volatile("red.global.add.v4.f32 [%0], {%1,%2,%3,%4};" \
                 :: "l"(ptr), "f"(v0), "f"(v1), "f"(v2), "f"(v3) : "memory")

// mma.sync core for k_final: warp covers 16 rows x 64 cols over K=128.
__device__ __forceinline__ void mma_core(uint32_t aH, uint32_t bH,
                                         uint32_t aDelta, uint32_t bDelta,
                                         float acc[8][4]) {
    #pragma unroll
    for (int ks = 0; ks < 8; ks++) {
        uint32_t ao = aH + ks * 32;
        uint32_t ah0, ah1, ah2, ah3, al0, al1, al2, al3;
        LDMX4(ah0, ah1, ah2, ah3, ao);
        LDMX4(al0, al1, al2, al3, ao + aDelta);
        uint32_t br = bH + ks * (16 * AST * 2);
        #pragma unroll
        for (int nt = 0; nt < 8; nt++) {
            uint32_t ba = br + nt * 16;
            uint32_t bh0, bh1, bl0, bl1;
            LDMX2T(bh0, bh1, ba);
            LDMX2T(bl0, bl1, ba + bDelta);
            MMA_BF16(acc[nt], al0, al1, al2, al3, bh0, bh1);
            MMA_BF16(acc[nt], ah0, ah1, ah2, ah3, bl0, bl1);
            MMA_BF16(acc[nt], ah0, ah1, ah2, ah3, bh0, bh1);
        }
    }
}
__device__ __forceinline__ void load_B_at(char* smem, uint32_t bhOff, uint32_t blOff,
                                          int widx, int tid, int nthreads) {
    __nv_bfloat16* Bh = (__nv_bfloat16*)(smem + bhOff);
    __nv_bfloat16* Bl = (__nv_bfloat16*)(smem + blOff);
    const uint4* srcH = (const uint4*)(g_Wh + (size_t)widx * D * D);
    const uint4* srcL = (const uint4*)(g_Wl + (size_t)widx * D * D);
    for (int f = tid; f < 2048; f += nthreads) {
        int k = f >> 4, c8 = (f & 15) * 8;
        *(uint4*)(Bh + k * AST + c8) = srcH[f];
        *(uint4*)(Bl + k * AST + c8) = srcL[f];
    }
}

// ---------------------------------------------------------------------------
__global__ void k_split_w(const float* __restrict__ Wt, const float* __restrict__ We2,
                          const float* __restrict__ Wself, const float* __restrict__ W1) {
    int i = blockIdx.x * blockDim.x + threadIdx.x;
    int idx = i * 2;
    if (idx >= 7 * D * D) return;
    int m = idx / (D * D), r = idx % (D * D);
    const float* src = (m < 4) ? (Wt + (size_t)m * D * D + r)
                     : (m == 4 ? We2 + r : (m == 5 ? Wself + r : W1 + r));
    float2 v = *(const float2*)src;
    __nv_bfloat16 h0, l0, h1, l1;
    split_bf(v.x, h0, l0); split_bf(v.y, h1, l1);
    *(__nv_bfloat162*)(g_Wh + idx) = __halves2bfloat162(h0, h1);
    *(__nv_bfloat162*)(g_Wl + idx) = __halves2bfloat162(l0, l1);
}

// ---------------------------------------------------------------------------
__global__ void k_zero(int N) {
    size_t nA4 = (size_t)TTYPES * N * D / 4;
    size_t nS4 = (size_t)N * D / 4;
    size_t nC  = (size_t)TTYPES * N;
    size_t stride = (size_t)gridDim.x * blockDim.x;
    size_t i0 = (size_t)blockIdx.x * blockDim.x + threadIdx.x;
    float4 z = make_float4(0.f, 0.f, 0.f, 0.f);
    float4* A4 = (float4*)g_A;
    float4* S4 = (float4*)g_S;
    for (size_t i = i0; i < nA4; i += stride) A4[i] = z;
    for (size_t i = i0; i < nS4; i += stride) S4[i] = z;
    for (size_t i = i0; i < nC;  i += stride) g_cnt[i] = 0;
}

// ---------------------------------------------------------------------------
// One warp per edge: g_A[type][row] += x[col] (red.v4); counts.
__global__ void k_scatter(const float* __restrict__ x, const int* __restrict__ ei,
                          const int* __restrict__ et, int N, int E) {
    int w = (int)(((size_t)blockIdx.x * blockDim.x + threadIdx.x) >> 5);
    int lane = threadIdx.x & 31;
    if (w >= E) return;
    int row = __ldg(ei + w);
    int col = __ldg(ei + E + w);
    int t   = __ldg(et + w);
    float4 v = *(const float4*)(x + (size_t)col * D + lane * 4);
    float* p = g_A + ((size_t)t * N + row) * D + lane * 4;
    REDV4(p, v.x, v.y, v.z, v.w);
    if (lane == 0) atomicAdd(&g_cnt[t * N + row], 1);
}

// ---------------------------------------------------------------------------
// Persistent edge MLP with REGISTER-RESIDENT W1 fragments.
// 256 threads, 8 warps = 2 row-groups (64 rows) x 4 col-groups (32 cols).
// H = relu(ef @ W1 + b1), scatter-add into g_S[dst].
__global__ void __launch_bounds__(256, 1)
k_edge_mlp(const float* __restrict__ ef, const int* __restrict__ ei,
           const float* __restrict__ b1, int E, int ntiles) {
    extern __shared__ char smem[];
    uint32_t sb = smem_u32(smem);
    __nv_bfloat16* Ah = (__nv_bfloat16*)smem;
    __nv_bfloat16* Al = (__nv_bfloat16*)(smem + P_HALF);
    float* S = (float*)(smem + P_S);           // [128][132]
    int tid = threadIdx.x, wid = tid >> 5, lane = tid & 31;
    int rg = wid & 1, cg = wid >> 1;           // 2 x 4 warp grid

    // Stage W1 (pre-split) into smem, pull B fragments into registers, then
    // the staging area is reused for the A tile.
    load_B_at(smem, 0, P_HALF, 6, tid, 256);
    __syncthreads();
    uint32_t bh_r[8][4][2], bl_r[8][4][2];
    #pragma unroll
    for (int ks = 0; ks < 8; ks++) {
        #pragma unroll
        for (int nt = 0; nt < 4; nt++) {
            uint32_t ba = sb + (uint32_t)(((ks * 16 + (lane & 15)) * AST
                                           + cg * 32 + nt * 8) * 2);
            LDMX2T(bh_r[ks][nt][0], bh_r[ks][nt][1], ba);
            LDMX2T(bl_r[ks][nt][0], bl_r[ks][nt][1], ba + P_HALF);
        }
    }
    __syncthreads();   // all warps done reading staging before A overwrites it

    float4 bb = __ldg((const float4*)b1 + lane);

    for (int tile = blockIdx.x; tile < ntiles; tile += gridDim.x) {
        size_t e0 = (size_t)tile * 128;
        // convert: LDG ef -> split bf16 -> smem A (each thread 16 float4)
        #pragma unroll 4
        for (int t = 0; t < 16; t++) {
            int idx = tid + t * 256;
            int row = idx >> 4, c4 = (idx & 15) * 8;   // 16 float4 per row? no:
            // 128 rows x 32 float4/row, 256 threads -> idx in [0,4096)
            row = idx >> 5; c4 = (idx & 31) * 4;
            size_t e = e0 + row;
            float4 v = make_float4(0.f, 0.f, 0.f, 0.f);
            if (e < (size_t)E) v = *(const float4*)(ef + e * D + c4);
            store4_split(Ah + row * AST, Al + row * AST, c4, v);
        }
        __syncthreads();

        // MMA: acc[rt][nt][4], B from registers, A via ldmatrix
        float acc[4][4][4] = {};
        #pragma unroll
        for (int ks = 0; ks < 8; ks++) {
            #pragma unroll
            for (int rt = 0; rt < 4; rt++) {
                uint32_t ao = sb + (uint32_t)(((rg * 64 + rt * 16 + (lane & 15)) * AST
                                               + (lane >> 4) * 8 + ks * 16) * 2);
                uint32_t ah0, ah1, ah2, ah3, al0, al1, al2, al3;
                LDMX4(ah0, ah1, ah2, ah3, ao);
                LDMX4(al0, al1, al2, al3, ao + P_HALF);
                #pragma unroll
                for (int nt = 0; nt < 4; nt++) {
                    MMA_BF16(acc[rt][nt], al0, al1, al2, al3,
                             bh_r[ks][nt][0], bh_r[ks][nt][1]);
                    MMA_BF16(acc[rt][nt], ah0, ah1, ah2, ah3,
                             bl_r[ks][nt][0], bl_r[ks][nt][1]);
                    MMA_BF16(acc[rt][nt], ah0, ah1, ah2, ah3,
                             bh_r[ks][nt][0], bh_r[ks][nt][1]);
                }
            }
        }

        // acc -> S staging (separate region; full rows for contiguous scatter)
        {
            int cp = (lane & 3) * 2;
            #pragma unroll
            for (int rt = 0; rt < 4; rt++) {
                int r0 = rg * 64 + rt * 16 + (lane >> 2);
                #pragma unroll
                for (int nt = 0; nt < 4; nt++) {
                    int c = cg * 32 + nt * 8 + cp;
                    S[r0 * 132 + c]           = acc[rt][nt][0];
                    S[r0 * 132 + c + 1]       = acc[rt][nt][1];
                    S[(r0 + 8) * 132 + c]     = acc[rt][nt][2];
                    S[(r0 + 8) * 132 + c + 1] = acc[rt][nt][3];
                }
            }
        }
        __syncthreads();

        // scatter: warp w handles edges [w*16, w*16+16), coalesced red.v4
        #pragma unroll
        for (int it = 0; it < 16; it++) {
            int el = wid * 16 + it;
            size_t e = e0 + el;
            if (e < (size_t)E) {
                int dst = __ldg(ei + e);
                const float* Sr = S + el * 132 + lane * 4;
                float4 sv = *(const float4*)Sr;
                float v0 = fmaxf(sv.x + bb.x, 0.f);
                float v1 = fmaxf(sv.y + bb.y, 0.f);
                float v2 = fmaxf(sv.z + bb.z, 0.f);
                float v3 = fmaxf(sv.w + bb.w, 0.f);
                REDV4(g_S + (size_t)dst * D + lane * 4, v0, v1, v2, v3);
            }
        }
        __syncthreads();
    }
}

// ---------------------------------------------------------------------------
// out[n] = sum over 6 K-segments + count-weighted biases, LayerNorm, ReLU.
// 64-node tiles, 2 blocks/SM (R5-proven).
__global__ void __launch_bounds__(256, 2)
k_final(const float* __restrict__ x,
        const float* __restrict__ b_types, const float* __restrict__ b_self,
        const float* __restrict__ b_e2,
        const float* __restrict__ ln_g, const float* __restrict__ ln_b,
        float* __restrict__ out, int N) {
    extern __shared__ char smem[];
    __shared__ float Ps[1024];
    __nv_bfloat16* Ah = (__nv_bfloat16*)smem;
    __nv_bfloat16* Al = (__nv_bfloat16*)(smem + F_A);
    int tid = threadIdx.x, wid = tid >> 5, lane = tid & 31;
    int n0 = blockIdx.x * 64;
    int rw = (wid & 3) * 16, ch = (wid >> 2) * 64;

    for (int f = tid; f < 1024; f += 256) {
        float v;
        if (f < 512)      v = b_types[f];
        else if (f < 640) v = b_e2[f - 512];
        else if (f < 768) v = b_self[f - 640];
        else if (f < 896) v = ln_g[f - 768];
        else              v = ln_b[f - 896];
        Ps[f] = v;
    }

    uint32_t aH = smem_u32(Ah + (rw + (lane & 15)) * AST + ((lane >> 4) * 8));
    uint32_t bH = smem_u32((__nv_bfloat16*)(smem + 2 * F_A) + (lane & 15) * AST + ch);

    float acc[8][4] = {};
    for (int seg = 0; seg < 6; seg++) {
        const float* Ab = (seg < 4) ? (g_A + (size_t)seg * N * D)
                                    : (seg == 4 ? g_S : x);
        __syncthreads();
        for (int idx = tid; idx < 64 * 32; idx += 256) {
            int r = idx >> 5, c4 = (idx & 31) * 4;
            float4 v = make_float4(0.f, 0.f, 0.f, 0.f);
            int n = n0 + r;
            if (n < N) v = *(const float4*)(Ab + (size_t)n * D + c4);
            store4_split(Ah + r * AST, Al + r * AST, c4, v);
        }
        load_B_at(smem, 2 * F_A, 2 * F_A + F_B, seg, tid, 256);
        __syncthreads();
        mma_core(aH, bH, F_A, F_B, acc);
    }

    // Epilogue via smem round-trip (full rows needed for LayerNorm).
    __syncthreads();
    float* S = (float*)smem;   // [64][132]
    {
        int r0 = rw + (lane >> 2);
        int cp = (lane & 3) * 2;
        #pragma unroll
        for (int nt = 0; nt < 8; nt++) {
            int c = ch + nt * 8 + cp;
            S[r0 * 132 + c]           = acc[nt][0];
            S[r0 * 132 + c + 1]       = acc[nt][1];
            S[(r0 + 8) * 132 + c]     = acc[nt][2];
            S[(r0 + 8) * 132 + c + 1] = acc[nt][3];
        }
    }
    __syncthreads();

    for (int it = 0; it < 8; it++) {
        int r = wid * 8 + it;
        int n = n0 + r;
        bool valid = n < N;
        float c0 = 0.f, c1 = 0.f, c2 = 0.f, c3 = 0.f;
        if (valid) {
            c0 = (float)__ldg(&g_cnt[0 * N + n]);
            c1 = (float)__ldg(&g_cnt[1 * N + n]);
            c2 = (float)__ldg(&g_cnt[2 * N + n]);
            c3 = (float)__ldg(&g_cnt[3 * N + n]);
        }
        float ct = c0 + c1 + c2 + c3;
        float v[4];
        float s1 = 0.f, s2 = 0.f;
        #pragma unroll
        for (int j = 0; j < 4; j++) {
            int col = lane * 4 + j;
            float val = S[r * 132 + col]
                + c0 * Ps[0 * D + col] + c1 * Ps[1 * D + col]
                + c2 * Ps[2 * D + col] + c3 * Ps[3 * D + col]
                + ct * Ps[512 + col] + Ps[640 + col];
            v[j] = val;
            s1 += val;
            s2 += val * val;
        }
        #pragma unroll
        for (int m = 1; m < 32; m <<= 1) {
            s1 += __shfl_xor_sync(0xffffffff, s1, m);
            s2 += __shfl_xor_sync(0xffffffff, s2, m);
        }
        float mean = s1 * (1.f / D);
        float var  = s2 * (1.f / D) - mean * mean;
        float inv  = rsqrtf(var + 1e-5f);
        if (valid) {
            float4 o;
            #pragma unroll
            for (int j = 0; j < 4; j++) {
                int col = lane * 4 + j;
                float rres = (v[j] - mean) * inv * Ps[768 + col] + Ps[896 + col];
                (&o.x)[j] = rres > 0.f ? rres : 0.f;
            }
            *(float4*)(out + (size_t)n * D + lane * 4) = o;
        }
    }
}

// ---------------------------------------------------------------------------
extern "C" void kernel_launch(void* const* d_in, const int* in_sizes, int n_in,
                              void* d_out, int out_size) {
    const float* x   = (const float*)d_in[0];
    const int*   ei  = (const int*)d_in[1];
    const int*   et  = (const int*)d_in[2];
    const float* ef  = (const float*)d_in[3];
    const float* Wt  = (const float*)d_in[4];
    const float* bt  = (const float*)d_in[5];
    const float* Ws  = (const float*)d_in[6];
    const float* bs  = (const float*)d_in[7];
    const float* W1  = (const float*)d_in[8];
    const float* b1  = (const float*)d_in[9];
    const float* W2  = (const float*)d_in[10];
    const float* b2  = (const float*)d_in[11];
    const float* lg  = (const float*)d_in[12];
    const float* lb  = (const float*)d_in[13];
    float* out = (float*)d_out;

    int N = in_sizes[0] / D;
    int E = in_sizes[2];
    int ntiles = (E + 127) / 128;
    int mlp_grid = ntiles < 148 ? ntiles : 148;

    cudaFuncSetAttribute(k_edge_mlp, cudaFuncAttributeMaxDynamicSharedMemorySize, P_SMEM);
    cudaFuncSetAttribute(k_final,    cudaFuncAttributeMaxDynamicSharedMemorySize, F_SMEM);

    k_split_w<<<(7 * D * D / 2 + 255) / 256, 256>>>(Wt, W2, Ws, W1);
    k_zero<<<2048, 256>>>(N);
    k_scatter<<<(E + 7) / 8, 256>>>(x, ei, et, N, E);
    k_edge_mlp<<<mlp_grid, 256, P_SMEM>>>(ef, ei, b1, E, ntiles);
    k_final<<<(N + 63) / 64, 256, F_SMEM>>>(x, bt, bs, b2, lg, lb, out, N);
}

// round 12
// speedup vs baseline: 1.4602x; 1.1479x over previous
#include <cuda_runtime.h>
#include <cuda_bf16.h>
#include <cstdint>

#define D 128
#define NMAX 50000
#define TTYPES 4
#define AST 136                      // bf16 elems per smem row (ldmatrix pad)

// k_final smem layout (64-row tiles, 2 blocks/SM)
#define F_A 17408                    // 64*136*2
#define F_B 34816                    // 128*136*2
#define F_SMEM (2 * F_A + 2 * F_B)   // 104448

// k_edge_mlp persistent layout (128-row tiles, reg-resident B, cp.async staging)
// Ah [0,34816) Al [34816,69632) S [69632,137216) RAW [137216,202752)
#define P_HALF 34816
#define P_S    69632
#define P_RAW  137216
#define P_SMEM 202752

// Scratch (device globals: allocation-free rule)
__device__ float g_A[(size_t)TTYPES * NMAX * D];   // per-type scatter of x[col]
__device__ float g_S[(size_t)NMAX * D];            // scatter of relu(ef@W1+b1)
__device__ int   g_cnt[TTYPES * NMAX];             // per (type,node) edge counts
// pre-split weights: [0..3]=W_types, [4]=W_e2, [5]=W_self, [6]=W1
__device__ __nv_bfloat16 g_Wh[7 * D * D];
__device__ __nv_bfloat16 g_Wl[7 * D * D];

// ---------------------------------------------------------------------------
__device__ __forceinline__ uint32_t smem_u32(const void* p) {
    return (uint32_t)__cvta_generic_to_shared(p);
}
__device__ __forceinline__ void split_bf(float a, __nv_bfloat16& h, __nv_bfloat16& l) {
    h = __float2bfloat16_rn(a);
    l = __float2bfloat16_rn(a - __bfloat162float(h));
}
__device__ __forceinline__ void store4_split(__nv_bfloat16* Hrow, __nv_bfloat16* Lrow,
                                             int c, float4 v) {
    __nv_bfloat16 h0, l0, h1, l1, h2, l2, h3, l3;
    split_bf(v.x, h0, l0); split_bf(v.y, h1, l1);
    split_bf(v.z, h2, l2); split_bf(v.w, h3, l3);
    *(__nv_bfloat162*)(Hrow + c)     = __halves2bfloat162(h0, h1);
    *(__nv_bfloat162*)(Hrow + c + 2) = __halves2bfloat162(h2, h3);
    *(__nv_bfloat162*)(Lrow + c)     = __halves2bfloat162(l0, l1);
    *(__nv_bfloat162*)(Lrow + c + 2) = __halves2bfloat162(l2, l3);
}

#define LDMX4(r0, r1, r2, r3, addr) \
    asm volatile("ldmatrix.sync.aligned.m8n8.x4.shared.b16 {%0,%1,%2,%3},[%4];" \
                 : "=r"(r0), "=r"(r1), "=r"(r2), "=r"(r3) : "r"(addr))
#define LDMX2T(r0, r1, addr) \
    asm volatile("ldmatrix.sync.aligned.m8n8.x2.trans.shared.b16 {%0,%1},[%2];" \
                 : "=r"(r0), "=r"(r1) : "r"(addr))
#define MMA_BF16(d, a0, a1, a2, a3, b0, b1) \
    asm volatile("mma.sync.aligned.m16n8k16.row.col.f32.bf16.bf16.f32 " \
                 "{%0,%1,%2,%3},{%4,%5,%6,%7},{%8,%9},{%0,%1,%2,%3};" \
                 : "+f"(d[0]), "+f"(d[1]), "+f"(d[2]), "+f"(d[3]) \
                 : "r"(a0), "r"(a1), "r"(a2), "r"(a3), "r"(b0), "r"(b1))
#define REDV4(ptr, v0, v1, v2, v3) \
    asm volatile("red.global.add.v4.f32 [%0], {%1,%2,%3,%4};" \
                 :: "l"(ptr), "f"(v0), "f"(v1), "f"(v2), "f"(v3) : "memory")
#define CP_ASYNC16(dst, src, sz) \
    asm volatile("cp.async.cg.shared.global [%0], [%1], 16, %2;" \
                 :: "r"(dst), "l"(src), "r"(sz) : "memory")
#define CP_COMMIT() asm volatile("cp.async.commit_group;" ::: "memory")
#define CP_WAIT0()  asm volatile("cp.async.wait_group 0;" ::: "memory")

// mma.sync core for k_final: warp covers 16 rows x 64 cols over K=128.
__device__ __forceinline__ void mma_core(uint32_t aH, uint32_t bH,
                                         uint32_t aDelta, uint32_t bDelta,
                                         float acc[8][4]) {
    #pragma unroll
    for (int ks = 0; ks < 8; ks++) {
        uint32_t ao = aH + ks * 32;
        uint32_t ah0, ah1, ah2, ah3, al0, al1, al2, al3;
        LDMX4(ah0, ah1, ah2, ah3, ao);
        LDMX4(al0, al1, al2, al3, ao + aDelta);
        uint32_t br = bH + ks * (16 * AST * 2);
        #pragma unroll
        for (int nt = 0; nt < 8; nt++) {
            uint32_t ba = br + nt * 16;
            uint32_t bh0, bh1, bl0, bl1;
            LDMX2T(bh0, bh1, ba);
            LDMX2T(bl0, bl1, ba + bDelta);
            MMA_BF16(acc[nt], al0, al1, al2, al3, bh0, bh1);
            MMA_BF16(acc[nt], ah0, ah1, ah2, ah3, bl0, bl1);
            MMA_BF16(acc[nt], ah0, ah1, ah2, ah3, bh0, bh1);
        }
    }
}
__device__ __forceinline__ void load_B_at(char* smem, uint32_t bhOff, uint32_t blOff,
                                          int widx, int tid, int nthreads) {
    __nv_bfloat16* Bh = (__nv_bfloat16*)(smem + bhOff);
    __nv_bfloat16* Bl = (__nv_bfloat16*)(smem + blOff);
    const uint4* srcH = (const uint4*)(g_Wh + (size_t)widx * D * D);
    const uint4* srcL = (const uint4*)(g_Wl + (size_t)widx * D * D);
    for (int f = tid; f < 2048; f += nthreads) {
        int k = f >> 4, c8 = (f & 15) * 8;
        *(uint4*)(Bh + k * AST + c8) = srcH[f];
        *(uint4*)(Bl + k * AST + c8) = srcL[f];
    }
}

// ---------------------------------------------------------------------------
__global__ void k_split_w(const float* __restrict__ Wt, const float* __restrict__ We2,
                          const float* __restrict__ Wself, const float* __restrict__ W1) {
    int i = blockIdx.x * blockDim.x + threadIdx.x;
    int idx = i * 2;
    if (idx >= 7 * D * D) return;
    int m = idx / (D * D), r = idx % (D * D);
    const float* src = (m < 4) ? (Wt + (size_t)m * D * D + r)
                     : (m == 4 ? We2 + r : (m == 5 ? Wself + r : W1 + r));
    float2 v = *(const float2*)src;
    __nv_bfloat16 h0, l0, h1, l1;
    split_bf(v.x, h0, l0); split_bf(v.y, h1, l1);
    *(__nv_bfloat162*)(g_Wh + idx) = __halves2bfloat162(h0, h1);
    *(__nv_bfloat162*)(g_Wl + idx) = __halves2bfloat162(l0, l1);
}

// ---------------------------------------------------------------------------
__global__ void k_zero(int N) {
    size_t nA4 = (size_t)TTYPES * N * D / 4;
    size_t nS4 = (size_t)N * D / 4;
    size_t nC  = (size_t)TTYPES * N;
    size_t stride = (size_t)gridDim.x * blockDim.x;
    size_t i0 = (size_t)blockIdx.x * blockDim.x + threadIdx.x;
    float4 z = make_float4(0.f, 0.f, 0.f, 0.f);
    float4* A4 = (float4*)g_A;
    float4* S4 = (float4*)g_S;
    for (size_t i = i0; i < nA4; i += stride) A4[i] = z;
    for (size_t i = i0; i < nS4; i += stride) S4[i] = z;
    for (size_t i = i0; i < nC;  i += stride) g_cnt[i] = 0;
}

// ---------------------------------------------------------------------------
// One warp per edge: g_A[type][row] += x[col] (red.v4); counts.
__global__ void k_scatter(const float* __restrict__ x, const int* __restrict__ ei,
                          const int* __restrict__ et, int N, int E) {
    int w = (int)(((size_t)blockIdx.x * blockDim.x + threadIdx.x) >> 5);
    int lane = threadIdx.x & 31;
    if (w >= E) return;
    int row = __ldg(ei + w);
    int col = __ldg(ei + E + w);
    int t   = __ldg(et + w);
    float4 v = *(const float4*)(x + (size_t)col * D + lane * 4);
    float* p = g_A + ((size_t)t * N + row) * D + lane * 4;
    REDV4(p, v.x, v.y, v.z, v.w);
    if (lane == 0) atomicAdd(&g_cnt[t * N + row], 1);
}

// ---------------------------------------------------------------------------
// Issue cp.async for one tile's raw ef fp32 -> RAW staging (zfill OOB rows).
__device__ __forceinline__ void stage_tile(char* smem, const float* __restrict__ ef,
                                           int tile, int ntiles, int E, int tid) {
    if (tile >= ntiles) return;
    size_t e0 = (size_t)tile * 128;
    uint32_t raw = smem_u32(smem + P_RAW);
    #pragma unroll
    for (int i = 0; i < 16; i++) {
        int idx = tid + i * 256;
        int row = idx >> 5, c4 = (idx & 31) * 4;
        size_t e = e0 + row;
        uint32_t sz = (e < (size_t)E) ? 16u : 0u;
        CP_ASYNC16(raw + idx * 16, ef + e * D + c4, sz);
    }
    CP_COMMIT();
}

// Persistent edge MLP: reg-resident W1 fragments + cp.async staged input.
// 256 threads, 8 warps = 2 row-groups (64 rows) x 4 col-groups (32 cols).
__global__ void __launch_bounds__(256, 1)
k_edge_mlp(const float* __restrict__ ef, const int* __restrict__ ei,
           const float* __restrict__ b1, int E, int ntiles) {
    extern __shared__ char smem[];
    uint32_t sb = smem_u32(smem);
    __nv_bfloat16* Ah = (__nv_bfloat16*)smem;
    __nv_bfloat16* Al = (__nv_bfloat16*)(smem + P_HALF);
    float* S   = (float*)(smem + P_S);         // [128][132]
    float* RAW = (float*)(smem + P_RAW);       // [128][128]
    int tid = threadIdx.x, wid = tid >> 5, lane = tid & 31;
    int rg = wid & 1, cg = wid >> 1;           // 2 x 4 warp grid

    // Prologue fetch of the first tile overlaps B-fragment setup.
    stage_tile(smem, ef, blockIdx.x, ntiles, E, tid);

    // Stage W1 into A region, pull B fragments into registers.
    load_B_at(smem, 0, P_HALF, 6, tid, 256);
    __syncthreads();
    uint32_t bh_r[8][4][2], bl_r[8][4][2];
    #pragma unroll
    for (int ks = 0; ks < 8; ks++) {
        #pragma unroll
        for (int nt = 0; nt < 4; nt++) {
            uint32_t ba = sb + (uint32_t)(((ks * 16 + (lane & 15)) * AST
                                           + cg * 32 + nt * 8) * 2);
            LDMX2T(bh_r[ks][nt][0], bh_r[ks][nt][1], ba);
            LDMX2T(bl_r[ks][nt][0], bl_r[ks][nt][1], ba + P_HALF);
        }
    }

    float4 bb = __ldg((const float4*)b1 + lane);

    for (int tile = blockIdx.x; tile < ntiles; tile += gridDim.x) {
        size_t e0 = (size_t)tile * 128;
        CP_WAIT0();
        __syncthreads();   // staging ready; B-frag reads / prior MMA+scatter done

        // convert: RAW smem fp32 -> split bf16 A
        #pragma unroll 4
        for (int t = 0; t < 16; t++) {
            int idx = tid + t * 256;
            int row = idx >> 5, c4 = (idx & 31) * 4;
            float4 v = *(const float4*)(RAW + idx * 4);
            store4_split(Ah + row * AST, Al + row * AST, c4, v);
        }
        __syncthreads();   // A complete; staging fully consumed

        // prefetch next tile under the MMA (global -> smem, no regs)
        stage_tile(smem, ef, tile + (int)gridDim.x, ntiles, E, tid);

        // MMA: acc[rt][nt][4], B from registers, A via ldmatrix
        float acc[4][4][4] = {};
        #pragma unroll
        for (int ks = 0; ks < 8; ks++) {
            #pragma unroll
            for (int rt = 0; rt < 4; rt++) {
                uint32_t ao = sb + (uint32_t)(((rg * 64 + rt * 16 + (lane & 15)) * AST
                                               + (lane >> 4) * 8 + ks * 16) * 2);
                uint32_t ah0, ah1, ah2, ah3, al0, al1, al2, al3;
                LDMX4(ah0, ah1, ah2, ah3, ao);
                LDMX4(al0, al1, al2, al3, ao + P_HALF);
                #pragma unroll
                for (int nt = 0; nt < 4; nt++) {
                    MMA_BF16(acc[rt][nt], al0, al1, al2, al3,
                             bh_r[ks][nt][0], bh_r[ks][nt][1]);
                    MMA_BF16(acc[rt][nt], ah0, ah1, ah2, ah3,
                             bl_r[ks][nt][0], bl_r[ks][nt][1]);
                    MMA_BF16(acc[rt][nt], ah0, ah1, ah2, ah3,
                             bh_r[ks][nt][0], bh_r[ks][nt][1]);
                }
            }
        }

        // acc -> S staging (separate region; full rows for contiguous scatter)
        {
            int cp = (lane & 3) * 2;
            #pragma unroll
            for (int rt = 0; rt < 4; rt++) {
                int r0 = rg * 64 + rt * 16 + (lane >> 2);
                #pragma unroll
                for (int nt = 0; nt < 4; nt++) {
                    int c = cg * 32 + nt * 8 + cp;
                    S[r0 * 132 + c]           = acc[rt][nt][0];
                    S[r0 * 132 + c + 1]       = acc[rt][nt][1];
                    S[(r0 + 8) * 132 + c]     = acc[rt][nt][2];
                    S[(r0 + 8) * 132 + c + 1] = acc[rt][nt][3];
                }
            }
        }
        __syncthreads();   // S complete

        // scatter: warp w handles edges [w*16, w*16+16), coalesced red.v4
        #pragma unroll
        for (int it = 0; it < 16; it++) {
            int el = wid * 16 + it;
            size_t e = e0 + el;
            if (e < (size_t)E) {
                int dst = __ldg(ei + e);
                const float* Sr = S + el * 132 + lane * 4;
                float4 sv = *(const float4*)Sr;
                float v0 = fmaxf(sv.x + bb.x, 0.f);
                float v1 = fmaxf(sv.y + bb.y, 0.f);
                float v2 = fmaxf(sv.z + bb.z, 0.f);
                float v3 = fmaxf(sv.w + bb.w, 0.f);
                REDV4(g_S + (size_t)dst * D + lane * 4, v0, v1, v2, v3);
            }
        }
    }
}

// ---------------------------------------------------------------------------
// out[n] = sum over 6 K-segments + count-weighted biases, LayerNorm, ReLU.
// 64-node tiles, 2 blocks/SM.
__global__ void __launch_bounds__(256, 2)
k_final(const float* __restrict__ x,
        const float* __restrict__ b_types, const float* __restrict__ b_self,
        const float* __restrict__ b_e2,
        const float* __restrict__ ln_g, const float* __restrict__ ln_b,
        float* __restrict__ out, int N) {
    extern __shared__ char smem[];
    __shared__ float Ps[1024];
    __nv_bfloat16* Ah = (__nv_bfloat16*)smem;
    __nv_bfloat16* Al = (__nv_bfloat16*)(smem + F_A);
    int tid = threadIdx.x, wid = tid >> 5, lane = tid & 31;
    int n0 = blockIdx.x * 64;
    int rw = (wid & 3) * 16, ch = (wid >> 2) * 64;

    for (int f = tid; f < 1024; f += 256) {
        float v;
        if (f < 512)      v = b_types[f];
        else if (f < 640) v = b_e2[f - 512];
        else if (f < 768) v = b_self[f - 640];
        else if (f < 896) v = ln_g[f - 768];
        else              v = ln_b[f - 896];
        Ps[f] = v;
    }

    uint32_t aH = smem_u32(Ah + (rw + (lane & 15)) * AST + ((lane >> 4) * 8));
    uint32_t bH = smem_u32((__nv_bfloat16*)(smem + 2 * F_A) + (lane & 15) * AST + ch);

    float acc[8][4] = {};
    for (int seg = 0; seg < 6; seg++) {
        const float* Ab = (seg < 4) ? (g_A + (size_t)seg * N * D)
                                    : (seg == 4 ? g_S : x);
        __syncthreads();
        for (int idx = tid; idx < 64 * 32; idx += 256) {
            int r = idx >> 5, c4 = (idx & 31) * 4;
            float4 v = make_float4(0.f, 0.f, 0.f, 0.f);
            int n = n0 + r;
            if (n < N) v = *(const float4*)(Ab + (size_t)n * D + c4);
            store4_split(Ah + r * AST, Al + r * AST, c4, v);
        }
        load_B_at(smem, 2 * F_A, 2 * F_A + F_B, seg, tid, 256);
        __syncthreads();
        mma_core(aH, bH, F_A, F_B, acc);
    }

    // Epilogue via smem round-trip (full rows needed for LayerNorm).
    __syncthreads();
    float* S = (float*)smem;   // [64][132]
    {
        int r0 = rw + (lane >> 2);
        int cp = (lane & 3) * 2;
        #pragma unroll
        for (int nt = 0; nt < 8; nt++) {
            int c = ch + nt * 8 + cp;
            S[r0 * 132 + c]           = acc[nt][0];
            S[r0 * 132 + c + 1]       = acc[nt][1];
            S[(r0 + 8) * 132 + c]     = acc[nt][2];
            S[(r0 + 8) * 132 + c + 1] = acc[nt][3];
        }
    }
    __syncthreads();

    for (int it = 0; it < 8; it++) {
        int r = wid * 8 + it;
        int n = n0 + r;
        bool valid = n < N;
        float c0 = 0.f, c1 = 0.f, c2 = 0.f, c3 = 0.f;
        if (valid) {
            c0 = (float)__ldg(&g_cnt[0 * N + n]);
            c1 = (float)__ldg(&g_cnt[1 * N + n]);
            c2 = (float)__ldg(&g_cnt[2 * N + n]);
            c3 = (float)__ldg(&g_cnt[3 * N + n]);
        }
        float ct = c0 + c1 + c2 + c3;
        float v[4];
        float s1 = 0.f, s2 = 0.f;
        #pragma unroll
        for (int j = 0; j < 4; j++) {
            int col = lane * 4 + j;
            float val = S[r * 132 + col]
                + c0 * Ps[0 * D + col] + c1 * Ps[1 * D + col]
                + c2 * Ps[2 * D + col] + c3 * Ps[3 * D + col]
                + ct * Ps[512 + col] + Ps[640 + col];
            v[j] = val;
            s1 += val;
            s2 += val * val;
        }
        #pragma unroll
        for (int m = 1; m < 32; m <<= 1) {
            s1 += __shfl_xor_sync(0xffffffff, s1, m);
            s2 += __shfl_xor_sync(0xffffffff, s2, m);
        }
        float mean = s1 * (1.f / D);
        float var  = s2 * (1.f / D) - mean * mean;
        float inv  = rsqrtf(var + 1e-5f);
        if (valid) {
            float4 o;
            #pragma unroll
            for (int j = 0; j < 4; j++) {
                int col = lane * 4 + j;
                float rres = (v[j] - mean) * inv * Ps[768 + col] + Ps[896 + col];
                (&o.x)[j] = rres > 0.f ? rres : 0.f;
            }
            *(float4*)(out + (size_t)n * D + lane * 4) = o;
        }
    }
}

// ---------------------------------------------------------------------------
extern "C" void kernel_launch(void* const* d_in, const int* in_sizes, int n_in,
                              void* d_out, int out_size) {
    const float* x   = (const float*)d_in[0];
    const int*   ei  = (const int*)d_in[1];
    const int*   et  = (const int*)d_in[2];
    const float* ef  = (const float*)d_in[3];
    const float* Wt  = (const float*)d_in[4];
    const float* bt  = (const float*)d_in[5];
    const float* Ws  = (const float*)d_in[6];
    const float* bs  = (const float*)d_in[7];
    const float* W1  = (const float*)d_in[8];
    const float* b1  = (const float*)d_in[9];
    const float* W2  = (const float*)d_in[10];
    const float* b2  = (const float*)d_in[11];
    const float* lg  = (const float*)d_in[12];
    const float* lb  = (const float*)d_in[13];
    float* out = (float*)d_out;

    int N = in_sizes[0] / D;
    int E = in_sizes[2];
    int ntiles = (E + 127) / 128;
    int mlp_grid = ntiles < 148 ? ntiles : 148;

    cudaFuncSetAttribute(k_edge_mlp, cudaFuncAttributeMaxDynamicSharedMemorySize, P_SMEM);
    cudaFuncSetAttribute(k_final,    cudaFuncAttributeMaxDynamicSharedMemorySize, F_SMEM);

    k_split_w<<<(7 * D * D / 2 + 255) / 256, 256>>>(Wt, W2, Ws, W1);
    k_zero<<<2048, 256>>>(N);
    k_scatter<<<(E + 7) / 8, 256>>>(x, ei, et, N, E);
    k_edge_mlp<<<mlp_grid, 256, P_SMEM>>>(ef, ei, b1, E, ntiles);
    k_final<<<(N + 63) / 64, 256, F_SMEM>>>(x, bt, bs, b2, lg, lb, out, N);
}

// round 13
// speedup vs baseline: 1.4826x; 1.0153x over previous
#include <cuda_runtime.h>
#include <cuda_bf16.h>
#include <cstdint>

#define D 128
#define NMAX 50000
#define TTYPES 4
#define AST 136                      // bf16 elems per smem row (ldmatrix pad)

// k_edge_mlp persistent layout (128-row tiles, reg-resident B, cp.async staging)
#define P_HALF 34816
#define P_S    69632
#define P_RAW  137216
#define P_SMEM 202752

// k_final_v2 layout: Ah [0,34816) Al [34816,69632)
//                    Bbuf0 [69632,139264) Bbuf1 [139264,208896)
#define V_HALF 34816
#define V_B0   69632
#define V_BSZ  69632
#define V_SMEM 208896

// Scratch (device globals: allocation-free rule)
__device__ float g_A[(size_t)TTYPES * NMAX * D];   // per-type scatter of x[col]
__device__ float g_S[(size_t)NMAX * D];            // scatter of relu(ef@W1+b1)
__device__ int   g_cnt[TTYPES * NMAX];             // per (type,node) edge counts
// pre-split weights: [0..3]=W_types, [4]=W_e2, [5]=W_self, [6]=W1
__device__ __nv_bfloat16 g_Wh[7 * D * D];
__device__ __nv_bfloat16 g_Wl[7 * D * D];

// ---------------------------------------------------------------------------
__device__ __forceinline__ uint32_t smem_u32(const void* p) {
    return (uint32_t)__cvta_generic_to_shared(p);
}
__device__ __forceinline__ void split_bf(float a, __nv_bfloat16& h, __nv_bfloat16& l) {
    h = __float2bfloat16_rn(a);
    l = __float2bfloat16_rn(a - __bfloat162float(h));
}
__device__ __forceinline__ void store4_split(__nv_bfloat16* Hrow, __nv_bfloat16* Lrow,
                                             int c, float4 v) {
    __nv_bfloat16 h0, l0, h1, l1, h2, l2, h3, l3;
    split_bf(v.x, h0, l0); split_bf(v.y, h1, l1);
    split_bf(v.z, h2, l2); split_bf(v.w, h3, l3);
    *(__nv_bfloat162*)(Hrow + c)     = __halves2bfloat162(h0, h1);
    *(__nv_bfloat162*)(Hrow + c + 2) = __halves2bfloat162(h2, h3);
    *(__nv_bfloat162*)(Lrow + c)     = __halves2bfloat162(l0, l1);
    *(__nv_bfloat162*)(Lrow + c + 2) = __halves2bfloat162(l2, l3);
}

#define LDMX4(r0, r1, r2, r3, addr) \
    asm volatile("ldmatrix.sync.aligned.m8n8.x4.shared.b16 {%0,%1,%2,%3},[%4];" \
                 : "=r"(r0), "=r"(r1), "=r"(r2), "=r"(r3) : "r"(addr))
#define LDMX2T(r0, r1, addr) \
    asm volatile("ldmatrix.sync.aligned.m8n8.x2.trans.shared.b16 {%0,%1},[%2];" \
                 : "=r"(r0), "=r"(r1) : "r"(addr))
#define MMA_BF16(d, a0, a1, a2, a3, b0, b1) \
    asm volatile("mma.sync.aligned.m16n8k16.row.col.f32.bf16.bf16.f32 " \
                 "{%0,%1,%2,%3},{%4,%5,%6,%7},{%8,%9},{%0,%1,%2,%3};" \
                 : "+f"(d[0]), "+f"(d[1]), "+f"(d[2]), "+f"(d[3]) \
                 : "r"(a0), "r"(a1), "r"(a2), "r"(a3), "r"(b0), "r"(b1))
#define REDV4(ptr, v0, v1, v2, v3) \
    asm volatile("red.global.add.v4.f32 [%0], {%1,%2,%3,%4};" \
                 :: "l"(ptr), "f"(v0), "f"(v1), "f"(v2), "f"(v3) : "memory")
#define CP_ASYNC16(dst, src, sz) \
    asm volatile("cp.async.cg.shared.global [%0], [%1], 16, %2;" \
                 :: "r"(dst), "l"(src), "r"(sz) : "memory")
#define CP_COMMIT() asm volatile("cp.async.commit_group;" ::: "memory")
#define CP_WAIT0()  asm volatile("cp.async.wait_group 0;" ::: "memory")
#define CP_WAIT1()  asm volatile("cp.async.wait_group 1;" ::: "memory")

// ---------------------------------------------------------------------------
__global__ void k_split_w(const float* __restrict__ Wt, const float* __restrict__ We2,
                          const float* __restrict__ Wself, const float* __restrict__ W1) {
    int i = blockIdx.x * blockDim.x + threadIdx.x;
    int idx = i * 2;
    if (idx >= 7 * D * D) return;
    int m = idx / (D * D), r = idx % (D * D);
    const float* src = (m < 4) ? (Wt + (size_t)m * D * D + r)
                     : (m == 4 ? We2 + r : (m == 5 ? Wself + r : W1 + r));
    float2 v = *(const float2*)src;
    __nv_bfloat16 h0, l0, h1, l1;
    split_bf(v.x, h0, l0); split_bf(v.y, h1, l1);
    *(__nv_bfloat162*)(g_Wh + idx) = __halves2bfloat162(h0, h1);
    *(__nv_bfloat162*)(g_Wl + idx) = __halves2bfloat162(l0, l1);
}

// ---------------------------------------------------------------------------
__global__ void k_zero(int N) {
    size_t nA4 = (size_t)TTYPES * N * D / 4;
    size_t nS4 = (size_t)N * D / 4;
    size_t nC  = (size_t)TTYPES * N;
    size_t stride = (size_t)gridDim.x * blockDim.x;
    size_t i0 = (size_t)blockIdx.x * blockDim.x + threadIdx.x;
    float4 z = make_float4(0.f, 0.f, 0.f, 0.f);
    float4* A4 = (float4*)g_A;
    float4* S4 = (float4*)g_S;
    for (size_t i = i0; i < nA4; i += stride) A4[i] = z;
    for (size_t i = i0; i < nS4; i += stride) S4[i] = z;
    for (size_t i = i0; i < nC;  i += stride) g_cnt[i] = 0;
}

// ---------------------------------------------------------------------------
// One warp per edge: g_A[type][row] += x[col] (red.v4); counts.
__global__ void k_scatter(const float* __restrict__ x, const int* __restrict__ ei,
                          const int* __restrict__ et, int N, int E) {
    int w = (int)(((size_t)blockIdx.x * blockDim.x + threadIdx.x) >> 5);
    int lane = threadIdx.x & 31;
    if (w >= E) return;
    int row = __ldg(ei + w);
    int col = __ldg(ei + E + w);
    int t   = __ldg(et + w);
    float4 v = *(const float4*)(x + (size_t)col * D + lane * 4);
    float* p = g_A + ((size_t)t * N + row) * D + lane * 4;
    REDV4(p, v.x, v.y, v.z, v.w);
    if (lane == 0) atomicAdd(&g_cnt[t * N + row], 1);
}

// ---------------------------------------------------------------------------
// Issue cp.async for one mlp tile's raw ef fp32 -> RAW staging (zfill OOB rows).
__device__ __forceinline__ void stage_tile(char* smem, const float* __restrict__ ef,
                                           int tile, int ntiles, int E, int tid) {
    if (tile >= ntiles) return;
    size_t e0 = (size_t)tile * 128;
    uint32_t raw = smem_u32(smem + P_RAW);
    #pragma unroll
    for (int i = 0; i < 16; i++) {
        int idx = tid + i * 256;
        int row = idx >> 5, c4 = (idx & 31) * 4;
        size_t e = e0 + row;
        uint32_t sz = (e < (size_t)E) ? 16u : 0u;
        CP_ASYNC16(raw + idx * 16, ef + e * D + c4, sz);
    }
    CP_COMMIT();
}

// Persistent edge MLP: reg-resident W1 fragments + cp.async staged input.
__global__ void __launch_bounds__(256, 1)
k_edge_mlp(const float* __restrict__ ef, const int* __restrict__ ei,
           const float* __restrict__ b1, int E, int ntiles) {
    extern __shared__ char smem[];
    uint32_t sb = smem_u32(smem);
    __nv_bfloat16* Ah = (__nv_bfloat16*)smem;
    __nv_bfloat16* Al = (__nv_bfloat16*)(smem + P_HALF);
    float* S   = (float*)(smem + P_S);
    float* RAW = (float*)(smem + P_RAW);
    int tid = threadIdx.x, wid = tid >> 5, lane = tid & 31;
    int rg = wid & 1, cg = wid >> 1;

    stage_tile(smem, ef, blockIdx.x, ntiles, E, tid);

    // Stage W1 into A region, pull B fragments into registers.
    {
        __nv_bfloat16* Bh = (__nv_bfloat16*)smem;
        __nv_bfloat16* Bl = (__nv_bfloat16*)(smem + P_HALF);
        const uint4* srcH = (const uint4*)(g_Wh + (size_t)6 * D * D);
        const uint4* srcL = (const uint4*)(g_Wl + (size_t)6 * D * D);
        for (int f = tid; f < 2048; f += 256) {
            int k = f >> 4, c8 = (f & 15) * 8;
            *(uint4*)(Bh + k * AST + c8) = srcH[f];
            *(uint4*)(Bl + k * AST + c8) = srcL[f];
        }
    }
    __syncthreads();
    uint32_t bh_r[8][4][2], bl_r[8][4][2];
    #pragma unroll
    for (int ks = 0; ks < 8; ks++) {
        #pragma unroll
        for (int nt = 0; nt < 4; nt++) {
            uint32_t ba = sb + (uint32_t)(((ks * 16 + (lane & 15)) * AST
                                           + cg * 32 + nt * 8) * 2);
            LDMX2T(bh_r[ks][nt][0], bh_r[ks][nt][1], ba);
            LDMX2T(bl_r[ks][nt][0], bl_r[ks][nt][1], ba + P_HALF);
        }
    }

    float4 bb = __ldg((const float4*)b1 + lane);

    for (int tile = blockIdx.x; tile < ntiles; tile += gridDim.x) {
        size_t e0 = (size_t)tile * 128;
        CP_WAIT0();
        __syncthreads();

        #pragma unroll 4
        for (int t = 0; t < 16; t++) {
            int idx = tid + t * 256;
            int row = idx >> 5, c4 = (idx & 31) * 4;
            float4 v = *(const float4*)(RAW + idx * 4);
            store4_split(Ah + row * AST, Al + row * AST, c4, v);
        }
        __syncthreads();

        stage_tile(smem, ef, tile + (int)gridDim.x, ntiles, E, tid);

        float acc[4][4][4] = {};
        #pragma unroll
        for (int ks = 0; ks < 8; ks++) {
            #pragma unroll
            for (int rt = 0; rt < 4; rt++) {
                uint32_t ao = sb + (uint32_t)(((rg * 64 + rt * 16 + (lane & 15)) * AST
                                               + (lane >> 4) * 8 + ks * 16) * 2);
                uint32_t ah0, ah1, ah2, ah3, al0, al1, al2, al3;
                LDMX4(ah0, ah1, ah2, ah3, ao);
                LDMX4(al0, al1, al2, al3, ao + P_HALF);
                #pragma unroll
                for (int nt = 0; nt < 4; nt++) {
                    MMA_BF16(acc[rt][nt], al0, al1, al2, al3,
                             bh_r[ks][nt][0], bh_r[ks][nt][1]);
                    MMA_BF16(acc[rt][nt], ah0, ah1, ah2, ah3,
                             bl_r[ks][nt][0], bl_r[ks][nt][1]);
                    MMA_BF16(acc[rt][nt], ah0, ah1, ah2, ah3,
                             bh_r[ks][nt][0], bh_r[ks][nt][1]);
                }
            }
        }

        {
            int cp = (lane & 3) * 2;
            #pragma unroll
            for (int rt = 0; rt < 4; rt++) {
                int r0 = rg * 64 + rt * 16 + (lane >> 2);
                #pragma unroll
                for (int nt = 0; nt < 4; nt++) {
                    int c = cg * 32 + nt * 8 + cp;
                    S[r0 * 132 + c]           = acc[rt][nt][0];
                    S[r0 * 132 + c + 1]       = acc[rt][nt][1];
                    S[(r0 + 8) * 132 + c]     = acc[rt][nt][2];
                    S[(r0 + 8) * 132 + c + 1] = acc[rt][nt][3];
                }
            }
        }
        __syncthreads();

        #pragma unroll
        for (int it = 0; it < 16; it++) {
            int el = wid * 16 + it;
            size_t e = e0 + el;
            if (e < (size_t)E) {
                int dst = __ldg(ei + e);
                const float* Sr = S + el * 132 + lane * 4;
                float4 sv = *(const float4*)Sr;
                float v0 = fmaxf(sv.x + bb.x, 0.f);
                float v1 = fmaxf(sv.y + bb.y, 0.f);
                float v2 = fmaxf(sv.z + bb.z, 0.f);
                float v3 = fmaxf(sv.w + bb.w, 0.f);
                REDV4(g_S + (size_t)dst * D + lane * 4, v0, v1, v2, v3);
            }
        }
    }
}

// ---------------------------------------------------------------------------
// k_final_v2: 128-node tiles, 512 threads, cp.async double-buffered B,
// register-prefetched A. 6 K-segments, then biases + LayerNorm + ReLU.
__device__ __forceinline__ const float* seg_src(int seg, const float* x, int N) {
    return (seg < 4) ? (g_A + (size_t)seg * N * D) : (seg == 4 ? g_S : x);
}
__device__ __forceinline__ void prefA(float4 r[8], const float* __restrict__ Ab,
                                      int n0, int N, int tid) {
    #pragma unroll
    for (int t = 0; t < 8; t++) {
        int idx = tid + t * 512;
        int row = idx >> 5, c4 = (idx & 31) * 4;
        int n = n0 + row;
        float4 v = make_float4(0.f, 0.f, 0.f, 0.f);
        if (n < N) v = *(const float4*)(Ab + (size_t)n * D + c4);
        r[t] = v;
    }
}
__device__ __forceinline__ void stageB(char* smem, int buf, int seg, int tid) {
    uint32_t dh = smem_u32(smem + V_B0 + buf * V_BSZ);
    const uint4* srcH = (const uint4*)(g_Wh + (size_t)seg * D * D);
    const uint4* srcL = (const uint4*)(g_Wl + (size_t)seg * D * D);
    #pragma unroll
    for (int i = 0; i < 4; i++) {
        int f = tid + i * 512;
        int k = f >> 4, c8 = (f & 15) * 8;
        uint32_t off = (uint32_t)((k * AST + c8) * 2);
        CP_ASYNC16(dh + off, srcH + f, 16);
        CP_ASYNC16(dh + P_HALF + off, srcL + f, 16);
    }
    CP_COMMIT();
}

__global__ void __launch_bounds__(512, 1)
k_final(const float* __restrict__ x,
        const float* __restrict__ b_types, const float* __restrict__ b_self,
        const float* __restrict__ b_e2,
        const float* __restrict__ ln_g, const float* __restrict__ ln_b,
        float* __restrict__ out, int N) {
    extern __shared__ char smem[];
    __shared__ float Ps[1024];
    uint32_t sb = smem_u32(smem);
    __nv_bfloat16* Ah = (__nv_bfloat16*)smem;
    __nv_bfloat16* Al = (__nv_bfloat16*)(smem + V_HALF);
    int tid = threadIdx.x, wid = tid >> 5, lane = tid & 31;
    int n0 = blockIdx.x * 128;
    int rg = wid & 3, cg = wid >> 2;           // 4 x 4 warp grid

    for (int f = tid; f < 1024; f += 512) {
        float v;
        if (f < 512)      v = b_types[f];
        else if (f < 640) v = b_e2[f - 512];
        else if (f < 768) v = b_self[f - 640];
        else if (f < 896) v = ln_g[f - 768];
        else              v = ln_b[f - 896];
        Ps[f] = v;
    }

    stageB((char*)smem, 0, 0, tid);
    float4 r[8];
    prefA(r, seg_src(0, x, N), n0, N, tid);

    float acc[2][4][4] = {};
    #pragma unroll
    for (int seg = 0; seg < 6; seg++) {
        __syncthreads();   // previous MMA done reading Asplit (no-op cost seg0)
        // convert prefetched regs -> split A
        #pragma unroll
        for (int t = 0; t < 8; t++) {
            int idx = tid + t * 512;
            int row = idx >> 5, c4 = (idx & 31) * 4;
            store4_split(Ah + row * AST, Al + row * AST, c4, r[t]);
        }
        if (seg < 5) {
            stageB((char*)smem, (seg + 1) & 1, seg + 1, tid);
            prefA(r, seg_src(seg + 1, x, N), n0, N, tid);
            CP_WAIT1();    // B(seg) arrived; B(seg+1) still in flight
        } else {
            CP_WAIT0();
        }
        __syncthreads();

        uint32_t bBase = sb + (uint32_t)(V_B0 + (seg & 1) * V_BSZ);
        #pragma unroll
        for (int ks = 0; ks < 8; ks++) {
            uint32_t ah0, ah1, ah2, ah3, al0, al1, al2, al3;
            uint32_t bfr[4][2][2];
            #pragma unroll
            for (int nt = 0; nt < 4; nt++) {
                uint32_t ba = bBase + (uint32_t)(((ks * 16 + (lane & 15)) * AST
                                                  + cg * 32 + nt * 8) * 2);
                LDMX2T(bfr[nt][0][0], bfr[nt][0][1], ba);
                LDMX2T(bfr[nt][1][0], bfr[nt][1][1], ba + P_HALF);
            }
            #pragma unroll
            for (int rt = 0; rt < 2; rt++) {
                uint32_t ao = sb + (uint32_t)(((rg * 32 + rt * 16 + (lane & 15)) * AST
                                               + (lane >> 4) * 8 + ks * 16) * 2);
                LDMX4(ah0, ah1, ah2, ah3, ao);
                LDMX4(al0, al1, al2, al3, ao + V_HALF);
                #pragma unroll
                for (int nt = 0; nt < 4; nt++) {
                    MMA_BF16(acc[rt][nt], al0, al1, al2, al3,
                             bfr[nt][0][0], bfr[nt][0][1]);
                    MMA_BF16(acc[rt][nt], ah0, ah1, ah2, ah3,
                             bfr[nt][1][0], bfr[nt][1][1]);
                    MMA_BF16(acc[rt][nt], ah0, ah1, ah2, ah3,
                             bfr[nt][0][0], bfr[nt][0][1]);
                }
            }
        }
    }

    // Epilogue: acc -> S (overlay A region), then LN + ReLU + store.
    __syncthreads();
    float* S = (float*)smem;   // [128][132]
    {
        int cp = (lane & 3) * 2;
        #pragma unroll
        for (int rt = 0; rt < 2; rt++) {
            int r0 = rg * 32 + rt * 16 + (lane >> 2);
            #pragma unroll
            for (int nt = 0; nt < 4; nt++) {
                int c = cg * 32 + nt * 8 + cp;
                S[r0 * 132 + c]           = acc[rt][nt][0];
                S[r0 * 132 + c + 1]       = acc[rt][nt][1];
                S[(r0 + 8) * 132 + c]     = acc[rt][nt][2];
                S[(r0 + 8) * 132 + c + 1] = acc[rt][nt][3];
            }
        }
    }
    __syncthreads();

    for (int it = 0; it < 8; it++) {
        int rr = wid * 8 + it;
        int n = n0 + rr;
        bool valid = n < N;
        float c0 = 0.f, c1 = 0.f, c2 = 0.f, c3 = 0.f;
        if (valid) {
            c0 = (float)__ldg(&g_cnt[0 * N + n]);
            c1 = (float)__ldg(&g_cnt[1 * N + n]);
            c2 = (float)__ldg(&g_cnt[2 * N + n]);
            c3 = (float)__ldg(&g_cnt[3 * N + n]);
        }
        float ct = c0 + c1 + c2 + c3;
        float v[4];
        float s1 = 0.f, s2 = 0.f;
        #pragma unroll
        for (int j = 0; j < 4; j++) {
            int col = lane * 4 + j;
            float val = S[rr * 132 + col]
                + c0 * Ps[0 * D + col] + c1 * Ps[1 * D + col]
                + c2 * Ps[2 * D + col] + c3 * Ps[3 * D + col]
                + ct * Ps[512 + col] + Ps[640 + col];
            v[j] = val;
            s1 += val;
            s2 += val * val;
        }
        #pragma unroll
        for (int m = 1; m < 32; m <<= 1) {
            s1 += __shfl_xor_sync(0xffffffff, s1, m);
            s2 += __shfl_xor_sync(0xffffffff, s2, m);
        }
        float mean = s1 * (1.f / D);
        float var  = s2 * (1.f / D) - mean * mean;
        float inv  = rsqrtf(var + 1e-5f);
        if (valid) {
            float4 o;
            #pragma unroll
            for (int j = 0; j < 4; j++) {
                int col = lane * 4 + j;
                float rres = (v[j] - mean) * inv * Ps[768 + col] + Ps[896 + col];
                (&o.x)[j] = rres > 0.f ? rres : 0.f;
            }
            *(float4*)(out + (size_t)n * D + lane * 4) = o;
        }
    }
}

// ---------------------------------------------------------------------------
extern "C" void kernel_launch(void* const* d_in, const int* in_sizes, int n_in,
                              void* d_out, int out_size) {
    const float* x   = (const float*)d_in[0];
    const int*   ei  = (const int*)d_in[1];
    const int*   et  = (const int*)d_in[2];
    const float* ef  = (const float*)d_in[3];
    const float* Wt  = (const float*)d_in[4];
    const float* bt  = (const float*)d_in[5];
    const float* Ws  = (const float*)d_in[6];
    const float* bs  = (const float*)d_in[7];
    const float* W1  = (const float*)d_in[8];
    const float* b1  = (const float*)d_in[9];
    const float* W2  = (const float*)d_in[10];
    const float* b2  = (const float*)d_in[11];
    const float* lg  = (const float*)d_in[12];
    const float* lb  = (const float*)d_in[13];
    float* out = (float*)d_out;

    int N = in_sizes[0] / D;
    int E = in_sizes[2];
    int ntiles = (E + 127) / 128;
    int mlp_grid = ntiles < 148 ? ntiles : 148;

    cudaFuncSetAttribute(k_edge_mlp, cudaFuncAttributeMaxDynamicSharedMemorySize, P_SMEM);
    cudaFuncSetAttribute(k_final,    cudaFuncAttributeMaxDynamicSharedMemorySize, V_SMEM);

    k_split_w<<<(7 * D * D / 2 + 255) / 256, 256>>>(Wt, W2, Ws, W1);
    k_zero<<<2048, 256>>>(N);
    k_scatter<<<(E + 7) / 8, 256>>>(x, ei, et, N, E);
    k_edge_mlp<<<mlp_grid, 256, P_SMEM>>>(ef, ei, b1, E, ntiles);
    k_final<<<(N + 127) / 128, 512, V_SMEM>>>(x, bt, bs, b2, lg, lb, out, N);
}